// round 3
// baseline (speedup 1.0000x reference)
#include <cuda_runtime.h>
#include <stdint.h>

#define BB 8
#define NN 2048
#define CC 80
#define ROWF 84          // floats per box row: 4 box + 80 scores
#define NW 64            // uint32 words per mask row (2048/32)
#define OUT_K 200
#define SCORE_THR 0.01f

// Persistent scratch (no allocations allowed)
__device__ uint32_t           g_mask[BB][NN][NW];          // 4 MB  : IoU>0.5 bitmask
__device__ unsigned long long g_ckey[BB][CC][OUT_K];       // 1 MB  : (score_bits<<32)|~flatidx
__device__ int                g_cbox[BB][CC][OUT_K];       // 512 KB: original box index
__device__ int                g_ccnt[BB][CC];

// ---------------------------------------------------------------------------
// Kernel 1: per-batch IoU>0.5 bitmask.  grid(16, B), 128 threads: thread = row.
// ---------------------------------------------------------------------------
__global__ void iou_mask_kernel(const float* __restrict__ x) {
    const int b = blockIdx.y;
    const int i = blockIdx.x * blockDim.x + threadIdx.x;
    __shared__ float4 sb[NN];                               // 32 KB
    const float* xb = x + (size_t)b * NN * ROWF;
    for (int j = threadIdx.x; j < NN; j += blockDim.x) {
        const float* p = xb + j * ROWF;
        sb[j] = make_float4(p[0], p[1], p[2], p[3]);
    }
    __syncthreads();

    const float4 bi = sb[i];
    const float area_i = __fmul_rn(bi.z - bi.x, bi.w - bi.y);
    uint32_t* out = g_mask[b][i];
    uint32_t word = 0;
    for (int j = 0; j < NN; j++) {
        float4 bj = sb[j];
        float lx = fmaxf(bi.x, bj.x), ly = fmaxf(bi.y, bj.y);
        float rx = fminf(bi.z, bj.z), ry = fminf(bi.w, bj.w);
        float w  = fmaxf(__fadd_rn(rx, -lx), 0.f);
        float h  = fmaxf(__fadd_rn(ry, -ly), 0.f);
        float inter  = __fmul_rn(w, h);
        float area_j = __fmul_rn(bj.z - bj.x, bj.w - bj.y);
        float uni    = __fadd_rn(__fadd_rn(area_i, area_j), -inter);
        float iou    = __fdiv_rn(inter, fmaxf(uni, 1e-8f));
        if (iou > 0.5f) word |= 1u << (j & 31);
        if ((j & 31) == 31) { out[j >> 5] = word; word = 0; }
    }
}

// ---------------------------------------------------------------------------
// Kernel 2: one block per (class, batch).  grid(C, B), 256 threads.
//   sort 2048 keys (score desc, idx asc) -> bitmask NMS (early-exit at 200)
//   -> emit per-class candidate list (already sorted descending).
// ---------------------------------------------------------------------------
__global__ void nms_kernel(const float* __restrict__ x) {
    const int b = blockIdx.y, c = blockIdx.x;
    __shared__ unsigned long long sk[NN];                   // 16 KB
    __shared__ uint32_t kw[NW];
    __shared__ int s_i, s_cnt;

    const float* xb = x + (size_t)b * NN * ROWF;
    for (int i = threadIdx.x; i < NN; i += 256) {
        uint32_t sbits = __float_as_uint(xb[i * ROWF + 4 + c]);   // scores >= 0
        sk[i] = ((unsigned long long)sbits << 32)
              | (unsigned long long)(0xFFFFFFFFu - (uint32_t)i);  // idx tie-break
    }
    __syncthreads();

    // Bitonic sort, descending
    for (int k = 2; k <= NN; k <<= 1) {
        for (int j = k >> 1; j > 0; j >>= 1) {
            for (int i = threadIdx.x; i < NN; i += 256) {
                int ixj = i ^ j;
                if (ixj > i) {
                    unsigned long long a = sk[i], bv = sk[ixj];
                    bool desc = ((i & k) == 0);
                    if (desc ? (a < bv) : (a > bv)) { sk[i] = bv; sk[ixj] = a; }
                }
            }
            __syncthreads();
        }
    }

    // keep init: score > threshold
    for (int w = threadIdx.x; w < NW; w += 256) {
        uint32_t m = 0;
        for (int t = 0; t < 32; t++) {
            float s = __uint_as_float((uint32_t)(sk[w * 32 + t] >> 32));
            if (s > SCORE_THR) m |= 1u << t;
        }
        kw[w] = m;
    }
    if (threadIdx.x == 0) s_cnt = 0;
    __syncthreads();

    // Greedy NMS: leader advances cursor over kept bits; all threads suppress.
    int cur = -1;
    while (true) {
        if (threadIdx.x == 0) {
            int found = -1;
            if (s_cnt < OUT_K) {
                int start = cur + 1;
                int w = start >> 5;
                uint32_t m = (w < NW) ? (kw[w] & (0xFFFFFFFFu << (start & 31))) : 0u;
                while (true) {
                    if (m) { found = (w << 5) + __ffs(m) - 1; break; }
                    if (++w >= NW) break;
                    m = kw[w];
                }
            }
            if (found >= 0) {
                unsigned long long key = sk[found];
                uint32_t sbits = (uint32_t)(key >> 32);
                int oi = (int)(0xFFFFFFFFu - (uint32_t)(key & 0xFFFFFFFFu));
                int kc = s_cnt;
                uint32_t flat = (uint32_t)(c * NN + found);
                g_ckey[b][c][kc] = ((unsigned long long)sbits << 32)
                                 | (unsigned long long)(0xFFFFFFFFu - flat);
                g_cbox[b][c][kc] = oi;
                s_cnt = kc + 1;
            }
            s_i = found;
        }
        __syncthreads();
        int i = s_i;
        if (i < 0) break;
        int oi = (int)(0xFFFFFFFFu - (uint32_t)(sk[i] & 0xFFFFFFFFu));
        const uint32_t* __restrict__ row = g_mask[b][oi];
        for (int j = i + 1 + (int)threadIdx.x; j < NN; j += 256) {
            if ((kw[j >> 5] >> (j & 31)) & 1u) {
                int oj = (int)(0xFFFFFFFFu - (uint32_t)(sk[j] & 0xFFFFFFFFu));
                if ((row[oj >> 5] >> (oj & 31)) & 1u)
                    atomicAnd(&kw[j >> 5], ~(1u << (j & 31)));
            }
        }
        cur = i;
        __syncthreads();
    }
    if (threadIdx.x == 0) g_ccnt[b][c] = s_cnt;
}

// ---------------------------------------------------------------------------
// Kernel 3: per-batch top-200 merge of 80 sorted candidate lists.
//   grid(B), 128 threads; tournament: pick max head key, advance, emit row.
// ---------------------------------------------------------------------------
__global__ void topk_kernel(const float* __restrict__ x, float* __restrict__ out) {
    const int b = blockIdx.x;
    const int tid = threadIdx.x;
    __shared__ int p[CC];
    __shared__ unsigned long long red[128];
    __shared__ int s_cls;
    if (tid < CC) p[tid] = 0;
    __syncthreads();

    for (int k = 0; k < OUT_K; k++) {
        unsigned long long key = 0;
        if (tid < CC) {
            int pp = p[tid];
            if (pp < g_ccnt[b][tid]) key = g_ckey[b][tid][pp];
        }
        red[tid] = key;
        __syncthreads();
        for (int s = 64; s > 0; s >>= 1) {
            if (tid < s) { if (red[tid + s] > red[tid]) red[tid] = red[tid + s]; }
            __syncthreads();
        }
        unsigned long long mx = red[0];
        __syncthreads();
        if (key != 0 && key == mx) s_cls = tid;   // keys unique when nonzero
        if (mx == 0 && tid == 0)  s_cls = -1;
        __syncthreads();
        int cls = s_cls;
        if (tid == 0) {
            float* o = out + ((size_t)b * OUT_K + k) * 6;
            if (cls < 0) {
                o[0] = o[1] = o[2] = o[3] = o[4] = o[5] = 0.f;
            } else {
                int pp = p[cls];
                int bi = g_cbox[b][cls][pp];
                p[cls] = pp + 1;
                const float* bx = x + ((size_t)b * NN + bi) * ROWF;
                o[0] = (float)cls;
                o[1] = __uint_as_float((uint32_t)(mx >> 32));
                o[2] = fminf(fmaxf(bx[0], 0.f), 1.f);
                o[3] = fminf(fmaxf(bx[1], 0.f), 1.f);
                o[4] = fminf(fmaxf(bx[2], 0.f), 1.f);
                o[5] = fminf(fmaxf(bx[3], 0.f), 1.f);
            }
        }
        __syncthreads();
    }
}

extern "C" void kernel_launch(void* const* d_in, const int* in_sizes, int n_in,
                              void* d_out, int out_size) {
    const float* x = (const float*)d_in[0];
    float* out = (float*)d_out;
    (void)in_sizes; (void)n_in; (void)out_size;

    dim3 g1(NN / 128, BB);
    iou_mask_kernel<<<g1, 128>>>(x);
    dim3 g2(CC, BB);
    nms_kernel<<<g2, 256>>>(x);
    topk_kernel<<<BB, 128>>>(x, out);
}

// round 4
// speedup vs baseline: 2.8017x; 2.8017x over previous
#include <cuda_runtime.h>
#include <stdint.h>

#define BB 8
#define NN 2048
#define CC 80
#define ROWF 84          // floats per box row: 4 box + 80 scores
#define NW 64            // uint32 words per mask row (2048/32)
#define OUT_K 200
#define SCORE_THR 0.01f
#define FULLM 0xFFFFFFFFu

// Persistent scratch (no allocations allowed)
__device__ uint32_t           g_mask[BB][NN][NW];          // 4 MB  : IoU>0.5 bitmask
__device__ unsigned long long g_ckey[BB][CC][OUT_K];       // (score_bits<<32)|~flatidx
__device__ int                g_cbox[BB][CC][OUT_K];       // original box index
__device__ int                g_ccnt[BB][CC];

// swizzle to avoid 512B-stride bank conflicts on sb[]/sa[] reads
__device__ __forceinline__ int perm(int j) { return j ^ ((j >> 5) & 31); }

// ---------------------------------------------------------------------------
// Kernel 1: IoU>0.5 bitmask. grid(NN/4, B), 256 threads.
//   thread = (row r in 4-row tile, 32-col word w). Boxes+areas staged in smem.
// ---------------------------------------------------------------------------
__global__ void iou_mask_kernel(const float* __restrict__ x) {
    const int b = blockIdx.y;
    const int r = threadIdx.x >> 6;        // 0..3
    const int w = threadIdx.x & 63;        // 0..63
    const int i = blockIdx.x * 4 + r;

    __shared__ float4 sb[NN];              // 32 KB (swizzled)
    __shared__ float  sa[NN];              // 8 KB  (swizzled)

    const float* xb = x + (size_t)b * NN * ROWF;
    for (int j = threadIdx.x; j < NN; j += 256) {
        float4 v = *reinterpret_cast<const float4*>(xb + (size_t)j * ROWF);
        int pj = perm(j);
        sb[pj] = v;
        sa[pj] = __fmul_rn(v.z - v.x, v.w - v.y);
    }
    __syncthreads();

    const float4 bi = sb[perm(i)];
    const float  ai = sa[perm(i)];
    uint32_t word = 0;
    const int j0 = w * 32;
#pragma unroll 8
    for (int t = 0; t < 32; t++) {
        int pj = perm(j0 + t);
        float4 bj = sb[pj];
        float aj  = sa[pj];
        float lx = fmaxf(bi.x, bj.x), ly = fmaxf(bi.y, bj.y);
        float rx = fminf(bi.z, bj.z), ry = fminf(bi.w, bj.w);
        float ww = fmaxf(__fadd_rn(rx, -lx), 0.f);
        float hh = fmaxf(__fadd_rn(ry, -ly), 0.f);
        float inter = __fmul_rn(ww, hh);
        float uni   = __fadd_rn(__fadd_rn(ai, aj), -inter);
        float iou   = __fdiv_rn(inter, fmaxf(uni, 1e-8f));
        if (iou > 0.5f) word |= 1u << t;
    }
    g_mask[b][i][w] = word;
}

// ---------------------------------------------------------------------------
// Kernel 2: one block per (class, batch). grid(C, B), 256 threads.
//   bitonic sort 2048 64-bit keys (score desc, idx asc) in smem,
//   then warp 0 alone runs bitmask NMS (alive mask in registers).
// ---------------------------------------------------------------------------
__global__ void nms_kernel(const float* __restrict__ x) {
    const int b = blockIdx.y, c = blockIdx.x;
    __shared__ unsigned long long sk[NN];                   // 16 KB

    const float* xb = x + (size_t)b * NN * ROWF;
    for (int i = threadIdx.x; i < NN; i += 256) {
        uint32_t sbits = __float_as_uint(xb[(size_t)i * ROWF + 4 + c]); // scores >= 0
        sk[i] = ((unsigned long long)sbits << 32)
              | (unsigned long long)(FULLM - (uint32_t)i);  // idx tie-break
    }
    __syncthreads();

    // Bitonic sort, descending
    for (int k = 2; k <= NN; k <<= 1) {
        for (int j = k >> 1; j > 0; j >>= 1) {
            for (int i = threadIdx.x; i < NN; i += 256) {
                int ixj = i ^ j;
                if (ixj > i) {
                    unsigned long long a = sk[i], bv = sk[ixj];
                    bool desc = ((i & k) == 0);
                    if (desc ? (a < bv) : (a > bv)) { sk[i] = bv; sk[ixj] = a; }
                }
            }
            __syncthreads();
        }
    }

    if (threadIdx.x >= 32) return;          // warp 0 finishes alone
    const int lane = threadIdx.x;

    // alive bitmask over ORIGINAL indices: lane owns words 2*lane, 2*lane+1
    uint32_t a0 = FULLM, a1 = FULLM;
    int kept = 0;
    int p = 0;
    const uint32_t* mb = &g_mask[b][0][0];

    while (p < NN && kept < OUT_K) {
        int pp = p + lane;
        unsigned long long key = (pp < NN) ? sk[pp] : 0ull;
        float s = __uint_as_float((uint32_t)(key >> 32));
        bool sok = (pp < NN) && (s > SCORE_THR);
        int oi  = (int)(FULLM - (uint32_t)(key & FULLM));
        int wrd = (oi >> 5) & 63;
        uint32_t v0 = __shfl_sync(FULLM, a0, wrd >> 1);
        uint32_t v1 = __shfl_sync(FULLM, a1, wrd >> 1);
        uint32_t av = (wrd & 1) ? v1 : v0;
        bool alive = (av >> (oi & 31)) & 1u;

        uint32_t bal_s = __ballot_sync(FULLM, sok);
        uint32_t cand  = __ballot_sync(FULLM, sok && alive);
        if (cand == 0) {
            if (bal_s != FULLM) break;      // sorted: everything later fails score too
            p += 32;
            continue;
        }
        int l  = __ffs(cand) - 1;
        int pf = p + l;
        int oif = __shfl_sync(FULLM, oi, l);
        unsigned long long keyf = __shfl_sync(FULLM, key, l);
        if (lane == 0) {
            uint32_t sbits = (uint32_t)(keyf >> 32);
            uint32_t flat  = (uint32_t)(c * NN + pf);
            g_ckey[b][c][kept] = ((unsigned long long)sbits << 32)
                               | (unsigned long long)(FULLM - flat);
            g_cbox[b][c][kept] = oif;
        }
        kept++;
        const uint32_t* __restrict__ row = mb + (size_t)oif * NW;
        a0 &= ~row[2 * lane];
        a1 &= ~row[2 * lane + 1];           // self-bit in row clears oif from alive
        p = pf + 1;
    }
    if (lane == 0) g_ccnt[b][c] = kept;
}

// ---------------------------------------------------------------------------
// Kernel 3: per-batch top-200 merge of 80 sorted lists. grid(B), 32 threads.
//   Register-resident tournament: lane owns up to 3 class lists.
// ---------------------------------------------------------------------------
__global__ void topk_kernel(const float* __restrict__ x, float* __restrict__ out) {
    const int b = blockIdx.x;
    const int lane = threadIdx.x;

    int cnt[3]; int ptr[3]; unsigned long long cur[3];
#pragma unroll
    for (int s = 0; s < 3; s++) {
        int c = lane + 32 * s;
        if (c < CC) {
            cnt[s] = g_ccnt[b][c];
            ptr[s] = 0;
            cur[s] = (cnt[s] > 0) ? g_ckey[b][c][0] : 0ull;
        } else { cnt[s] = 0; ptr[s] = 0; cur[s] = 0ull; }
    }

    for (int k = 0; k < OUT_K; k++) {
        unsigned long long m = cur[0];
        if (cur[1] > m) m = cur[1];
        if (cur[2] > m) m = cur[2];
        unsigned long long g = m;
#pragma unroll
        for (int off = 16; off > 0; off >>= 1) {
            unsigned long long o = __shfl_xor_sync(FULLM, g, off);
            if (o > g) g = o;
        }
        uint32_t win = __ballot_sync(FULLM, (m == g) && (g != 0ull));
        float* o = out + ((size_t)b * OUT_K + k) * 6;
        if (g == 0ull) {
            if (lane < 6) o[lane] = 0.f;
        } else {
            int wl = __ffs(win) - 1;
            if (lane == wl) {
                int s = (cur[0] == g) ? 0 : (cur[1] == g) ? 1 : 2;
                int c = lane + 32 * s;
                int pp = ptr[s];
                int bi = g_cbox[b][c][pp];
                const float* bx = x + ((size_t)b * NN + bi) * ROWF;
                o[0] = (float)c;
                o[1] = __uint_as_float((uint32_t)(g >> 32));
                o[2] = fminf(fmaxf(bx[0], 0.f), 1.f);
                o[3] = fminf(fmaxf(bx[1], 0.f), 1.f);
                o[4] = fminf(fmaxf(bx[2], 0.f), 1.f);
                o[5] = fminf(fmaxf(bx[3], 0.f), 1.f);
                ptr[s] = pp + 1;
                cur[s] = (ptr[s] < cnt[s]) ? g_ckey[b][c][ptr[s]] : 0ull;
            }
        }
    }
}

extern "C" void kernel_launch(void* const* d_in, const int* in_sizes, int n_in,
                              void* d_out, int out_size) {
    const float* x = (const float*)d_in[0];
    float* out = (float*)d_out;
    (void)in_sizes; (void)n_in; (void)out_size;

    dim3 g1(NN / 4, BB);
    iou_mask_kernel<<<g1, 256>>>(x);
    dim3 g2(CC, BB);
    nms_kernel<<<g2, 256>>>(x);
    topk_kernel<<<BB, 32>>>(x, out);
}